// round 8
// baseline (speedup 1.0000x reference)
#include <cuda_runtime.h>
#include <cuda_fp16.h>
#include <cstdint>

#define BHX   32
#define SEQ   2048
#define DIMX  64
#define TOPKX 30

// Scratch fallbacks in case d_out holds only one of the two tuple outputs.
__device__ float g_attn_scratch[(size_t)BHX * SEQ * SEQ];
__device__ float g_ctx_scratch[(size_t)BHX * SEQ * DIMX];

// Pre-split fp16 hi/lo operands (built by split_kernel).
#define NELEM ((size_t)BHX * SEQ * DIMX)
__device__ __half g_qhi[NELEM];
__device__ __half g_qlo[NELEM];
__device__ __half g_khi[NELEM];
__device__ __half g_klo[NELEM];

// ===========================================================================
__device__ __forceinline__ uint32_t smem_u32(const void* p) {
    uint32_t a;
    asm("{ .reg .u64 t; cvta.to.shared.u64 t, %1; cvt.u32.u64 %0, t; }"
        : "=r"(a) : "l"(p));
    return a;
}

#define LDSM_X4(r0, r1, r2, r3, addr)                                        \
    asm volatile("ldmatrix.sync.aligned.m8n8.x4.shared.b16 {%0,%1,%2,%3}, [%4];" \
                 : "=r"(r0), "=r"(r1), "=r"(r2), "=r"(r3) : "r"(addr))

#define MMA_16816(d, a0, a1, a2, a3, b0, b1)                                 \
    asm volatile("mma.sync.aligned.m16n8k16.row.col.f32.f16.f16.f32 "        \
                 "{%0,%1,%2,%3}, {%4,%5,%6,%7}, {%8,%9}, {%0,%1,%2,%3};"     \
                 : "+f"((d)[0]), "+f"((d)[1]), "+f"((d)[2]), "+f"((d)[3])    \
                 : "r"(a0), "r"(a1), "r"(a2), "r"(a3), "r"(b0), "r"(b1))

#define CP_ASYNC16(dst, src)                                                 \
    asm volatile("cp.async.ca.shared.global [%0], [%1], 16;"                 \
                 :: "r"(dst), "l"(src))
#define CP_COMMIT()  asm volatile("cp.async.commit_group;" ::: "memory")
#define CP_WAIT0()   asm volatile("cp.async.wait_group 0;" ::: "memory")

// ===========================================================================
// K0: split q,k fp32 -> fp16 hi/lo buffers (row-major, same element order).
// ===========================================================================
__global__ __launch_bounds__(256) void split_kernel(
    const float* __restrict__ q, const float* __restrict__ k)
{
    const size_t idx = (size_t)blockIdx.x * 256 + threadIdx.x;  // float4 index
    float4 a = reinterpret_cast<const float4*>(q)[idx];
    float4 b = reinterpret_cast<const float4*>(k)[idx];
    {
        __half hx = __float2half_rn(a.x), hy = __float2half_rn(a.y);
        __half hz = __float2half_rn(a.z), hw = __float2half_rn(a.w);
        __half lx = __float2half_rn(a.x - __half2float(hx));
        __half ly = __float2half_rn(a.y - __half2float(hy));
        __half lz = __float2half_rn(a.z - __half2float(hz));
        __half lw = __float2half_rn(a.w - __half2float(hw));
        reinterpret_cast<uint2*>(g_qhi)[idx] = make_uint2(
            (uint32_t)__half_as_ushort(hx) | ((uint32_t)__half_as_ushort(hy) << 16),
            (uint32_t)__half_as_ushort(hz) | ((uint32_t)__half_as_ushort(hw) << 16));
        reinterpret_cast<uint2*>(g_qlo)[idx] = make_uint2(
            (uint32_t)__half_as_ushort(lx) | ((uint32_t)__half_as_ushort(ly) << 16),
            (uint32_t)__half_as_ushort(lz) | ((uint32_t)__half_as_ushort(lw) << 16));
    }
    {
        __half hx = __float2half_rn(b.x), hy = __float2half_rn(b.y);
        __half hz = __float2half_rn(b.z), hw = __float2half_rn(b.w);
        __half lx = __float2half_rn(b.x - __half2float(hx));
        __half ly = __float2half_rn(b.y - __half2float(hy));
        __half lz = __float2half_rn(b.z - __half2float(hz));
        __half lw = __float2half_rn(b.w - __half2float(hw));
        reinterpret_cast<uint2*>(g_khi)[idx] = make_uint2(
            (uint32_t)__half_as_ushort(hx) | ((uint32_t)__half_as_ushort(hy) << 16),
            (uint32_t)__half_as_ushort(hz) | ((uint32_t)__half_as_ushort(hw) << 16));
        reinterpret_cast<uint2*>(g_klo)[idx] = make_uint2(
            (uint32_t)__half_as_ushort(lx) | ((uint32_t)__half_as_ushort(ly) << 16),
            (uint32_t)__half_as_ushort(lz) | ((uint32_t)__half_as_ushort(lw) << 16));
    }
}

// ===========================================================================
// Kernel A': scores = q @ k^T via fp16x3 mma.sync, operands pre-split,
// loaded with cp.async (no cvt, no register staging). CTA tile 128x128.
// 8 warps (2x4), warp tile 64x32. MMA/epilogue identical to R4.
// ===========================================================================
#define A_HI_O  0
#define A_LO_O  16384
#define B_HI_O  32768
#define B_LO_O  49152
#define SMEM_A_DYN 65536

__global__ __launch_bounds__(256, 2) void gemm_hmma_kernel(
    float* __restrict__ scores)
{
    extern __shared__ char sm[];
    const uint32_t smb = smem_u32(sm);

    const int t    = threadIdx.x;
    const int wid  = t >> 5;
    const int lane = t & 31;

    const int colBase = blockIdx.x * 128;   // k rows (score cols)
    const int rowBase = blockIdx.y * 128;   // q rows
    const int bh      = blockIdx.z;

    // ---- cp.async: q,k hi/lo tiles (each 128 rows x 64 halves = 16KB) ----
    {
        const size_t qoff = ((size_t)bh * SEQ + rowBase) * DIMX;
        const size_t koff = ((size_t)bh * SEQ + colBase) * DIMX;
#pragma unroll
        for (int i = 0; i < 4; i++) {
            const int fi  = t + i * 256;            // 0..1023 chunk index
            const int row = fi >> 3;                // 0..127
            const int ch  = fi & 7;                 // 16B chunk in row
            const uint32_t dst = (uint32_t)(row * 128) + ((ch ^ (row & 7)) << 4);
            const size_t qs = qoff + (size_t)row * DIMX + ch * 8;
            const size_t ks = koff + (size_t)row * DIMX + ch * 8;
            CP_ASYNC16(smb + A_HI_O + dst, g_qhi + qs);
            CP_ASYNC16(smb + A_LO_O + dst, g_qlo + qs);
            CP_ASYNC16(smb + B_HI_O + dst, g_khi + ks);
            CP_ASYNC16(smb + B_LO_O + dst, g_klo + ks);
        }
    }
    CP_COMMIT();

    // ---- Warp tiles: 2 (M) x 4 (N) warps; warp tile 64x32 ----
    const int wm = wid >> 2;
    const int wn = wid & 3;

    float acc[4][4][4];
#pragma unroll
    for (int mi = 0; mi < 4; mi++)
#pragma unroll
        for (int ni = 0; ni < 4; ni++)
#pragma unroll
            for (int f = 0; f < 4; f++) acc[mi][ni][f] = 0.0f;

    uint32_t aRowByte[4];
    uint32_t aR7[4];
#pragma unroll
    for (int mi = 0; mi < 4; mi++) {
        const int row = wm * 64 + mi * 16 + (lane & 15);
        aRowByte[mi] = (uint32_t)(row * 128);
        aR7[mi] = (uint32_t)(row & 7);
    }
    const uint32_t aHiSel = (uint32_t)(lane >> 4);

    uint32_t bRowByte[2];
    uint32_t bR7[2];
#pragma unroll
    for (int ntp = 0; ntp < 2; ntp++) {
        const int row = wn * 32 + ntp * 16 + (lane & 7) + ((lane >> 4) << 3);
        bRowByte[ntp] = (uint32_t)(row * 128);
        bR7[ntp] = (uint32_t)(row & 7);
    }
    const uint32_t bHiSel = (uint32_t)((lane >> 3) & 1);

    CP_WAIT0();
    __syncthreads();

    const uint32_t aBase[3] = {smb + A_HI_O, smb + A_HI_O, smb + A_LO_O};
    const uint32_t bBase[3] = {smb + B_HI_O, smb + B_LO_O, smb + B_HI_O};

#pragma unroll
    for (int s = 0; s < 3; s++) {
        const uint32_t ab = aBase[s];
        const uint32_t bb = bBase[s];
#pragma unroll
        for (int kk = 0; kk < 4; kk++) {
            uint32_t a[4][4];
#pragma unroll
            for (int mi = 0; mi < 4; mi++) {
                const uint32_t chunk = (uint32_t)(kk * 2) + aHiSel;
                const uint32_t addr = ab + aRowByte[mi] + (((chunk ^ aR7[mi]) << 4));
                LDSM_X4(a[mi][0], a[mi][1], a[mi][2], a[mi][3], addr);
            }
            uint32_t b[2][4];
#pragma unroll
            for (int ntp = 0; ntp < 2; ntp++) {
                const uint32_t chunk = (uint32_t)(kk * 2) + bHiSel;
                const uint32_t addr = bb + bRowByte[ntp] + (((chunk ^ bR7[ntp]) << 4));
                LDSM_X4(b[ntp][0], b[ntp][1], b[ntp][2], b[ntp][3], addr);
            }
#pragma unroll
            for (int mi = 0; mi < 4; mi++) {
#pragma unroll
                for (int ni = 0; ni < 4; ni++) {
                    const uint32_t b0 = b[ni >> 1][(ni & 1) * 2 + 0];
                    const uint32_t b1 = b[ni >> 1][(ni & 1) * 2 + 1];
                    MMA_16816(acc[mi][ni], a[mi][0], a[mi][1], a[mi][2], a[mi][3], b0, b1);
                }
            }
        }
    }

    // ---- Epilogue: registers -> global (float2 stores, full 32B sectors) ----
    {
        const int r0 = lane >> 2;
        const int c0 = (lane & 3) * 2;
        float* gout = scores + ((size_t)bh * SEQ + rowBase + wm * 64) * SEQ
                      + colBase + wn * 32;
#pragma unroll
        for (int mi = 0; mi < 4; mi++) {
#pragma unroll
            for (int ni = 0; ni < 4; ni++) {
                float* p0 = gout + (size_t)(mi * 16 + r0) * SEQ + ni * 8 + c0;
                float* p1 = p0 + 8 * SEQ;
                *reinterpret_cast<float2*>(p0) = make_float2(acc[mi][ni][0], acc[mi][ni][1]);
                *reinterpret_cast<float2*>(p1) = make_float2(acc[mi][ni][2], acc[mi][ni][3]);
            }
        }
    }
}

// ===========================================================================
// Kernel B: per-row exact top-30 + masked softmax + scatter + context.
// (Byte-identical to R4's 319us kernel.)
// ===========================================================================
__device__ __forceinline__ unsigned f2key(float s) {
    unsigned u = __float_as_uint(s);
    return (u & 0x80000000u) ? ~u : (u | 0x80000000u);
}
__device__ __forceinline__ float key2f(unsigned key) {
    unsigned u = (key & 0x80000000u) ? (key ^ 0x80000000u) : ~key;
    return __uint_as_float(u);
}

__global__ __launch_bounds__(256) void topk_softmax_ctx_kernel(
    float* __restrict__ attn,
    const float* __restrict__ v,
    float* __restrict__ ctx)
{
    const int wid  = threadIdx.x >> 5;
    const int lane = threadIdx.x & 31;
    const size_t r = (size_t)blockIdx.x * 8 + wid;
    const int bh   = (int)(r >> 11);

    __shared__ int   scols[8][32];
    __shared__ float sws[8][32];

    float* rowp = attn + r * SEQ;
    const float4* rp4 = reinterpret_cast<const float4*>(rowp);

    unsigned a0 = 0, a1 = 0, a2 = 0, a3 = 0;
    int p0 = 0, p1 = 0, p2 = 0, p3 = 0;

#pragma unroll
    for (int i = 0; i < 16; i++) {
        float4 v4 = rp4[i * 32 + lane];
        float vv[4] = {v4.x, v4.y, v4.z, v4.w};
#pragma unroll
        for (int j = 0; j < 4; j++) {
            unsigned key = f2key(vv[j]);
            int pos = 4 * i + j;
            if (key > a3) {
                if (key > a2) {
                    a3 = a2; p3 = p2;
                    if (key > a1) {
                        a2 = a1; p2 = p1;
                        if (key > a0) { a1 = a0; p1 = p0; a0 = key; p0 = pos; }
                        else          { a1 = key; p1 = pos; }
                    } else { a2 = key; p2 = pos; }
                } else { a3 = key; p3 = pos; }
            }
        }
    }

    unsigned long long selmask = 0ull;
    int nvalid = 4;

    for (int it = 0; it < TOPKX; it++) {
        unsigned wmax = __reduce_max_sync(0xffffffffu, a0);
        unsigned ball = __ballot_sync(0xffffffffu, a0 == wmax);
        if (lane == (__ffs(ball) - 1)) {
            int col = (p0 >> 2) * 128 + lane * 4 + (p0 & 3);
            scols[wid][it] = col;
            sws[wid][it]   = key2f(wmax);
            selmask |= 1ull << p0;
            a0 = a1; p0 = p1; a1 = a2; p1 = p2; a2 = a3; p2 = p3; a3 = 0;
            nvalid--;
            if (nvalid == 0) {
#pragma unroll
                for (int i = 0; i < 16; i++) {
                    float4 v4 = rp4[i * 32 + lane];
                    float vv[4] = {v4.x, v4.y, v4.z, v4.w};
#pragma unroll
                    for (int j = 0; j < 4; j++) {
                        int pos = 4 * i + j;
                        if ((selmask >> pos) & 1ull) continue;
                        unsigned key = f2key(vv[j]);
                        if (key > a3) {
                            if (key > a2) {
                                a3 = a2; p3 = p2;
                                if (key > a1) {
                                    a2 = a1; p2 = p1;
                                    if (key > a0) { a1 = a0; p1 = p0; a0 = key; p0 = pos; }
                                    else          { a1 = key; p1 = pos; }
                                } else { a2 = key; p2 = pos; }
                            } else { a3 = key; p3 = pos; }
                        }
                    }
                }
                nvalid = 4;
            }
        }
    }
    __syncwarp();

    const float m = sws[wid][0];
    float e = 0.0f;
    if (lane < TOPKX) e = __expf(sws[wid][lane] - m);
    float z = e;
#pragma unroll
    for (int off = 16; off > 0; off >>= 1)
        z += __shfl_xor_sync(0xffffffffu, z, off);
    const float invZ = 1.0f / z;
    __syncwarp();
    if (lane < TOPKX) sws[wid][lane] = e * invZ;
    __syncwarp();

    const float4 z4 = make_float4(0.f, 0.f, 0.f, 0.f);
#pragma unroll
    for (int i = 0; i < 16; i++)
        reinterpret_cast<float4*>(rowp)[i * 32 + lane] = z4;
    __syncwarp();
    if (lane < TOPKX)
        rowp[scols[wid][lane]] = sws[wid][lane];

    float c0 = 0.0f, c1 = 0.0f;
    const float* vb = v + (size_t)bh * SEQ * DIMX;
#pragma unroll 5
    for (int j = 0; j < TOPKX; j++) {
        const float w  = sws[wid][j];
        const float* vp = vb + (size_t)scols[wid][j] * DIMX;
        c0 = fmaf(w, vp[lane], c0);
        c1 = fmaf(w, vp[lane + 32], c1);
    }
    ctx[r * DIMX + lane]      = c0;
    ctx[r * DIMX + lane + 32] = c1;
}

// ---------------------------------------------------------------------------
extern "C" void kernel_launch(void* const* d_in, const int* in_sizes, int n_in,
                              void* d_out, int out_size)
{
    const float* q = (const float*)d_in[0];
    const float* k = (const float*)d_in[1];
    const float* v = (const float*)d_in[2];

    const size_t CTX = (size_t)BHX * SEQ * DIMX;
    const size_t ATT = (size_t)BHX * SEQ * SEQ;

    float* outp = (float*)d_out;
    float* ctx;
    float* attn;
    if ((size_t)out_size >= CTX + ATT) {
        ctx  = outp;
        attn = outp + CTX;
    } else if ((size_t)out_size >= ATT) {
        attn = outp;
        cudaGetSymbolAddress((void**)&ctx, g_ctx_scratch);
    } else {
        ctx = outp;
        cudaGetSymbolAddress((void**)&attn, g_attn_scratch);
    }

    // K0: split q,k into fp16 hi/lo (1,048,576 float4 elements).
    split_kernel<<<4096, 256>>>(q, k);

    cudaFuncSetAttribute(gemm_hmma_kernel,
                         cudaFuncAttributeMaxDynamicSharedMemorySize, SMEM_A_DYN);

    dim3 gridA(SEQ / 128, SEQ / 128, BHX);   // 16 x 16 x 32 = 8192 CTAs
    gemm_hmma_kernel<<<gridA, 256, SMEM_A_DYN>>>(attn);

    dim3 gridB((BHX * SEQ) / 8);             // 8192 blocks
    topk_softmax_ctx_kernel<<<gridB, 256>>>(attn, v, ctx);
}

// round 9
// speedup vs baseline: 1.0713x; 1.0713x over previous
#include <cuda_runtime.h>
#include <cuda_fp16.h>
#include <cstdint>

#define BHX   32
#define SEQ   2048
#define DIMX  64
#define TOPKX 30

// Scratch fallbacks in case d_out holds only one of the two tuple outputs.
__device__ float g_attn_scratch[(size_t)BHX * SEQ * SEQ];
__device__ float g_ctx_scratch[(size_t)BHX * SEQ * DIMX];

// ===========================================================================
// Kernel A: scores = q @ k^T via fp16x3 mma.sync (Markidis split).
// CTA tile 128x128, K=64 resident. 8 warps (2x4), warp tile 64x32.
// (Byte-identical to R4's 213us kernel — at its HMMA+write floor.)
// ===========================================================================
__device__ __forceinline__ uint32_t smem_u32(const void* p) {
    uint32_t a;
    asm("{ .reg .u64 t; cvta.to.shared.u64 t, %1; cvt.u32.u64 %0, t; }"
        : "=r"(a) : "l"(p));
    return a;
}

#define LDSM_X4(r0, r1, r2, r3, addr)                                        \
    asm volatile("ldmatrix.sync.aligned.m8n8.x4.shared.b16 {%0,%1,%2,%3}, [%4];" \
                 : "=r"(r0), "=r"(r1), "=r"(r2), "=r"(r3) : "r"(addr))

#define MMA_16816(d, a0, a1, a2, a3, b0, b1)                                 \
    asm volatile("mma.sync.aligned.m16n8k16.row.col.f32.f16.f16.f32 "        \
                 "{%0,%1,%2,%3}, {%4,%5,%6,%7}, {%8,%9}, {%0,%1,%2,%3};"     \
                 : "+f"((d)[0]), "+f"((d)[1]), "+f"((d)[2]), "+f"((d)[3])    \
                 : "r"(a0), "r"(a1), "r"(a2), "r"(a3), "r"(b0), "r"(b1))

#define A_HI_O  0
#define A_LO_O  16384
#define B_HI_O  32768
#define B_LO_O  49152
#define SMEM_A_DYN 65536

__global__ __launch_bounds__(256, 2) void gemm_hmma_kernel(
    const float* __restrict__ q,
    const float* __restrict__ k,
    float* __restrict__ scores)
{
    extern __shared__ char sm[];
    const uint32_t smb = smem_u32(sm);

    const int t    = threadIdx.x;
    const int wid  = t >> 5;
    const int lane = t & 31;

    const int colBase = blockIdx.x * 128;
    const int rowBase = blockIdx.y * 128;
    const int bh      = blockIdx.z;

    // ---- Load + split q,k tiles (each 128 x 64 fp32 -> hi/lo fp16) ----
    {
        const float4* gq = reinterpret_cast<const float4*>(
            q + ((size_t)bh * SEQ + rowBase) * DIMX);
        const float4* gk = reinterpret_cast<const float4*>(
            k + ((size_t)bh * SEQ + colBase) * DIMX);
#pragma unroll
        for (int it = 0; it < 8; it++) {
            const int fi  = t + it * 256;
            const int row = fi >> 4;
            const int c4  = fi & 15;
            const uint32_t off = (uint32_t)(row * 128)
                + ((((c4 >> 1) ^ (row & 7)) << 4)) + ((c4 & 1) << 3);

            float4 a = gq[row * 16 + c4];
            {
                __half hx = __float2half_rn(a.x), hy = __float2half_rn(a.y);
                __half hz = __float2half_rn(a.z), hw = __float2half_rn(a.w);
                __half lx = __float2half_rn(a.x - __half2float(hx));
                __half ly = __float2half_rn(a.y - __half2float(hy));
                __half lz = __float2half_rn(a.z - __half2float(hz));
                __half lw = __float2half_rn(a.w - __half2float(hw));
                uint2 hv = make_uint2(
                    (uint32_t)__half_as_ushort(hx) | ((uint32_t)__half_as_ushort(hy) << 16),
                    (uint32_t)__half_as_ushort(hz) | ((uint32_t)__half_as_ushort(hw) << 16));
                uint2 lv = make_uint2(
                    (uint32_t)__half_as_ushort(lx) | ((uint32_t)__half_as_ushort(ly) << 16),
                    (uint32_t)__half_as_ushort(lz) | ((uint32_t)__half_as_ushort(lw) << 16));
                *reinterpret_cast<uint2*>(sm + A_HI_O + off) = hv;
                *reinterpret_cast<uint2*>(sm + A_LO_O + off) = lv;
            }
            float4 b = gk[row * 16 + c4];
            {
                __half hx = __float2half_rn(b.x), hy = __float2half_rn(b.y);
                __half hz = __float2half_rn(b.z), hw = __float2half_rn(b.w);
                __half lx = __float2half_rn(b.x - __half2float(hx));
                __half ly = __float2half_rn(b.y - __half2float(hy));
                __half lz = __float2half_rn(b.z - __half2float(hz));
                __half lw = __float2half_rn(b.w - __half2float(hw));
                uint2 hv = make_uint2(
                    (uint32_t)__half_as_ushort(hx) | ((uint32_t)__half_as_ushort(hy) << 16),
                    (uint32_t)__half_as_ushort(hz) | ((uint32_t)__half_as_ushort(hw) << 16));
                uint2 lv = make_uint2(
                    (uint32_t)__half_as_ushort(lx) | ((uint32_t)__half_as_ushort(ly) << 16),
                    (uint32_t)__half_as_ushort(lz) | ((uint32_t)__half_as_ushort(lw) << 16));
                *reinterpret_cast<uint2*>(sm + B_HI_O + off) = hv;
                *reinterpret_cast<uint2*>(sm + B_LO_O + off) = lv;
            }
        }
    }
    __syncthreads();

    const int wm = wid >> 2;
    const int wn = wid & 3;

    float acc[4][4][4];
#pragma unroll
    for (int mi = 0; mi < 4; mi++)
#pragma unroll
        for (int ni = 0; ni < 4; ni++)
#pragma unroll
            for (int f = 0; f < 4; f++) acc[mi][ni][f] = 0.0f;

    uint32_t aRowByte[4];
    uint32_t aR7[4];
#pragma unroll
    for (int mi = 0; mi < 4; mi++) {
        const int row = wm * 64 + mi * 16 + (lane & 15);
        aRowByte[mi] = (uint32_t)(row * 128);
        aR7[mi] = (uint32_t)(row & 7);
    }
    const uint32_t aHiSel = (uint32_t)(lane >> 4);

    uint32_t bRowByte[2];
    uint32_t bR7[2];
#pragma unroll
    for (int ntp = 0; ntp < 2; ntp++) {
        const int row = wn * 32 + ntp * 16 + (lane & 7) + ((lane >> 4) << 3);
        bRowByte[ntp] = (uint32_t)(row * 128);
        bR7[ntp] = (uint32_t)(row & 7);
    }
    const uint32_t bHiSel = (uint32_t)((lane >> 3) & 1);

    const uint32_t aBase[3] = {smb + A_HI_O, smb + A_HI_O, smb + A_LO_O};
    const uint32_t bBase[3] = {smb + B_HI_O, smb + B_LO_O, smb + B_HI_O};

#pragma unroll
    for (int s = 0; s < 3; s++) {
        const uint32_t ab = aBase[s];
        const uint32_t bb = bBase[s];
#pragma unroll
        for (int kk = 0; kk < 4; kk++) {
            uint32_t a[4][4];
#pragma unroll
            for (int mi = 0; mi < 4; mi++) {
                const uint32_t chunk = (uint32_t)(kk * 2) + aHiSel;
                const uint32_t addr = ab + aRowByte[mi] + (((chunk ^ aR7[mi]) << 4));
                LDSM_X4(a[mi][0], a[mi][1], a[mi][2], a[mi][3], addr);
            }
            uint32_t b[2][4];
#pragma unroll
            for (int ntp = 0; ntp < 2; ntp++) {
                const uint32_t chunk = (uint32_t)(kk * 2) + bHiSel;
                const uint32_t addr = bb + bRowByte[ntp] + (((chunk ^ bR7[ntp]) << 4));
                LDSM_X4(b[ntp][0], b[ntp][1], b[ntp][2], b[ntp][3], addr);
            }
#pragma unroll
            for (int mi = 0; mi < 4; mi++) {
#pragma unroll
                for (int ni = 0; ni < 4; ni++) {
                    const uint32_t b0 = b[ni >> 1][(ni & 1) * 2 + 0];
                    const uint32_t b1 = b[ni >> 1][(ni & 1) * 2 + 1];
                    MMA_16816(acc[mi][ni], a[mi][0], a[mi][1], a[mi][2], a[mi][3], b0, b1);
                }
            }
        }
    }

    {
        const int r0 = lane >> 2;
        const int c0 = (lane & 3) * 2;
        float* gout = scores + ((size_t)bh * SEQ + rowBase + wm * 64) * SEQ
                      + colBase + wn * 32;
#pragma unroll
        for (int mi = 0; mi < 4; mi++) {
#pragma unroll
            for (int ni = 0; ni < 4; ni++) {
                float* p0 = gout + (size_t)(mi * 16 + r0) * SEQ + ni * 8 + c0;
                float* p1 = p0 + 8 * SEQ;
                *reinterpret_cast<float2*>(p0) = make_float2(acc[mi][ni][0], acc[mi][ni][1]);
                *reinterpret_cast<float2*>(p1) = make_float2(acc[mi][ni][2], acc[mi][ni][3]);
            }
        }
    }
}

// ===========================================================================
// Kernel B: per-row exact top-30 — float-compare scan (no key cvt in hot
// loop), key cvt only at extraction for REDUX. Softmax + scatter + ctx.
// ===========================================================================
__device__ __forceinline__ unsigned f2key(float s) {
    unsigned u = __float_as_uint(s);
    return (u & 0x80000000u) ? ~u : (u | 0x80000000u);
}
__device__ __forceinline__ float key2f(unsigned key) {
    unsigned u = (key & 0x80000000u) ? (key ^ 0x80000000u) : ~key;
    return __uint_as_float(u);
}

__global__ __launch_bounds__(256) void topk_softmax_ctx_kernel(
    float* __restrict__ attn,
    const float* __restrict__ v,
    float* __restrict__ ctx)
{
    const int wid  = threadIdx.x >> 5;
    const int lane = threadIdx.x & 31;
    const size_t r = (size_t)blockIdx.x * 8 + wid;
    const int bh   = (int)(r >> 11);

    __shared__ int   scols[8][32];
    __shared__ float sws[8][32];

    float* rowp = attn + r * SEQ;
    const float4* rp4 = reinterpret_cast<const float4*>(rowp);

    const float NEG_INF = -__int_as_float(0x7F800000);

    // Per-lane sorted top-4 (descending floats) + positions.
    float s0 = NEG_INF, s1 = NEG_INF, s2 = NEG_INF, s3 = NEG_INF;
    int p0 = 0, p1 = 0, p2 = 0, p3 = 0;

#pragma unroll
    for (int i = 0; i < 16; i++) {
        float4 v4 = rp4[i * 32 + lane];
        float vv[4] = {v4.x, v4.y, v4.z, v4.w};
#pragma unroll
        for (int j = 0; j < 4; j++) {
            const float key = vv[j];
            const int pos = 4 * i + j;
            if (key > s3) {
                if (key > s2) {
                    s3 = s2; p3 = p2;
                    if (key > s1) {
                        s2 = s1; p2 = p1;
                        if (key > s0) { s1 = s0; p1 = p0; s0 = key; p0 = pos; }
                        else          { s1 = key; p1 = pos; }
                    } else { s2 = key; p2 = pos; }
                } else { s3 = key; p3 = pos; }
            }
        }
    }

    unsigned long long selmask = 0ull;
    int nvalid = 4;

    for (int it = 0; it < TOPKX; it++) {
        const unsigned hk = f2key(s0);
        unsigned wmax = __reduce_max_sync(0xffffffffu, hk);
        unsigned ball = __ballot_sync(0xffffffffu, hk == wmax);
        if (lane == (__ffs(ball) - 1)) {
            int col = (p0 >> 2) * 128 + lane * 4 + (p0 & 3);
            scols[wid][it] = col;
            sws[wid][it]   = s0;
            selmask |= 1ull << p0;
            s0 = s1; p0 = p1; s1 = s2; p1 = p2; s2 = s3; p2 = p3; s3 = NEG_INF;
            nvalid--;
            if (nvalid == 0) {
                // Exact rebuild: rescan this lane's 64 columns from global.
#pragma unroll
                for (int i = 0; i < 16; i++) {
                    float4 v4 = rp4[i * 32 + lane];
                    float vv[4] = {v4.x, v4.y, v4.z, v4.w};
#pragma unroll
                    for (int j = 0; j < 4; j++) {
                        const int pos = 4 * i + j;
                        if ((selmask >> pos) & 1ull) continue;
                        const float key = vv[j];
                        if (key > s3) {
                            if (key > s2) {
                                s3 = s2; p3 = p2;
                                if (key > s1) {
                                    s2 = s1; p2 = p1;
                                    if (key > s0) { s1 = s0; p1 = p0; s0 = key; p0 = pos; }
                                    else          { s1 = key; p1 = pos; }
                                } else { s2 = key; p2 = pos; }
                            } else { s3 = key; p3 = pos; }
                        }
                    }
                }
                nvalid = 4;
            }
        }
    }
    __syncwarp();

    const float m = sws[wid][0];
    float e = 0.0f;
    if (lane < TOPKX) e = __expf(sws[wid][lane] - m);
    float z = e;
#pragma unroll
    for (int off = 16; off > 0; off >>= 1)
        z += __shfl_xor_sync(0xffffffffu, z, off);
    const float invZ = 1.0f / z;
    __syncwarp();
    if (lane < TOPKX) sws[wid][lane] = e * invZ;
    __syncwarp();

    const float4 z4 = make_float4(0.f, 0.f, 0.f, 0.f);
#pragma unroll
    for (int i = 0; i < 16; i++)
        reinterpret_cast<float4*>(rowp)[i * 32 + lane] = z4;
    __syncwarp();
    if (lane < TOPKX)
        rowp[scols[wid][lane]] = sws[wid][lane];

    float c0 = 0.0f, c1 = 0.0f;
    const float* vb = v + (size_t)bh * SEQ * DIMX;
#pragma unroll 5
    for (int j = 0; j < TOPKX; j++) {
        const float w  = sws[wid][j];
        const float* vp = vb + (size_t)scols[wid][j] * DIMX;
        c0 = fmaf(w, vp[lane], c0);
        c1 = fmaf(w, vp[lane + 32], c1);
    }
    ctx[r * DIMX + lane]      = c0;
    ctx[r * DIMX + lane + 32] = c1;
}

// ---------------------------------------------------------------------------
extern "C" void kernel_launch(void* const* d_in, const int* in_sizes, int n_in,
                              void* d_out, int out_size)
{
    const float* q = (const float*)d_in[0];
    const float* k = (const float*)d_in[1];
    const float* v = (const float*)d_in[2];

    const size_t CTX = (size_t)BHX * SEQ * DIMX;
    const size_t ATT = (size_t)BHX * SEQ * SEQ;

    float* outp = (float*)d_out;
    float* ctx;
    float* attn;
    if ((size_t)out_size >= CTX + ATT) {
        ctx  = outp;
        attn = outp + CTX;
    } else if ((size_t)out_size >= ATT) {
        attn = outp;
        cudaGetSymbolAddress((void**)&ctx, g_ctx_scratch);
    } else {
        ctx = outp;
        cudaGetSymbolAddress((void**)&attn, g_attn_scratch);
    }

    cudaFuncSetAttribute(gemm_hmma_kernel,
                         cudaFuncAttributeMaxDynamicSharedMemorySize, SMEM_A_DYN);

    dim3 gridA(SEQ / 128, SEQ / 128, BHX);   // 16 x 16 x 32
    gemm_hmma_kernel<<<gridA, 256, SMEM_A_DYN>>>(q, k, attn);

    dim3 gridB((BHX * SEQ) / 8);             // 8192 blocks
    topk_softmax_ctx_kernel<<<gridB, 256>>>(attn, v, ctx);
}